// round 11
// baseline (speedup 1.0000x reference)
#include <cuda_runtime.h>

// CRPS over a 16-member ensemble:
//   out = mean_p( (1/N) sum_i |s_i - y|  -  (1/N^2) sum_{i<j} |s_i - s_j| )
// Identity: with v sorted ascending, sum_{i<j}|v_i - v_j| = sum_i (2i-15) v_i.
//
// R11: per-thread software pipeline. 4 pixels/thread (grid-strided).
// Batch 0 -> registers; batches 1-3 staged to smem via cp.async.ca 4B
// (no destination register => ptxas cannot re-serialize them; engine-tracked).
// Compute of batch k overlaps the in-flight loads of batches k+1..3 via
// ordered commit groups + wait_group. Each thread consumes only its own
// staged words, so no __syncthreads in the pipeline.

#define NS 16
#define PIXELS (4 * 1 * 256 * 256)      // 262144
#define PPT 4
#define NTHREADS (PIXELS / PPT)         // 65536
#define TPB 256
#define NBLOCKS (NTHREADS / TPB)        // 256
#define NSTAGE (PPT - 1)                // 3 staged batches
#define VALS (NS + 1)                   // 16 members + target

__device__ float g_partials[NBLOCKS];
__device__ unsigned int g_count = 0;

__device__ __forceinline__ void cmpswap(float& a, float& b) {
    float lo = fminf(a, b);
    float hi = fmaxf(a, b);
    a = lo; b = hi;
}

__device__ __forceinline__ float crps_vals(float (&v)[NS], float y) {
    float t1 = 0.f;
#pragma unroll
    for (int i = 0; i < NS; i++)
        t1 += fabsf(v[i] - y);

    // Batcher odd-even mergesort, 16 inputs, 63 comparators (alu pipe).
#define CS(a, b) cmpswap(v[a], v[b])
    CS(0,1);  CS(2,3);  CS(4,5);  CS(6,7);  CS(8,9);  CS(10,11); CS(12,13); CS(14,15);
    CS(0,2);  CS(1,3);  CS(4,6);  CS(5,7);  CS(8,10); CS(9,11);  CS(12,14); CS(13,15);
    CS(1,2);  CS(5,6);  CS(9,10); CS(13,14);
    CS(0,4);  CS(1,5);  CS(2,6);  CS(3,7);  CS(8,12); CS(9,13);  CS(10,14); CS(11,15);
    CS(2,4);  CS(3,5);  CS(10,12); CS(11,13);
    CS(1,2);  CS(3,4);  CS(5,6);  CS(9,10); CS(11,12); CS(13,14);
    CS(0,8);  CS(1,9);  CS(2,10); CS(3,11); CS(4,12); CS(5,13);  CS(6,14);  CS(7,15);
    CS(4,8);  CS(5,9);  CS(6,10); CS(7,11);
    CS(2,4);  CS(3,5);  CS(6,8);  CS(7,9);  CS(10,12); CS(11,13);
    CS(1,2);  CS(3,4);  CS(5,6);  CS(7,8);  CS(9,10);  CS(11,12); CS(13,14);
#undef CS

    float t2 = 0.f;
#pragma unroll
    for (int i = 0; i < NS; i++)
        t2 = fmaf((float)(2 * i - 15), v[i], t2);

    return t1 * (1.f / NS) - t2 * (1.f / (NS * NS));
}

__global__ __launch_bounds__(TPB) void crps_fused_kernel(
    const float* __restrict__ samples,   // [NS, PIXELS]
    const float* __restrict__ target,    // [PIXELS]
    float* __restrict__ out)
{
    // Staging: stage[b][i][tid], 3 * 17 * 256 floats = 52,224 B
    __shared__ float stage[NSTAGE][VALS][TPB];

    const int tid = threadIdx.x;
    const int t = blockIdx.x * TPB + tid;

    // ---- issue all staged batches first (engine-tracked, zero regs) ----
#pragma unroll
    for (int b = 0; b < NSTAGE; b++) {
        const int p = t + (b + 1) * NTHREADS;
#pragma unroll
        for (int i = 0; i < NS; i++) {
            unsigned d = (unsigned)__cvta_generic_to_shared(&stage[b][i][tid]);
            asm volatile("cp.async.ca.shared.global [%0], [%1], 4;"
                         :: "r"(d), "l"(samples + i * PIXELS + p));
        }
        unsigned dt = (unsigned)__cvta_generic_to_shared(&stage[b][NS][tid]);
        asm volatile("cp.async.ca.shared.global [%0], [%1], 4;"
                     :: "r"(dt), "l"(target + p));
        asm volatile("cp.async.commit_group;" ::: "memory");
    }

    // ---- batch 0: registers (overlaps with everything above) ----
    float v[NS];
#pragma unroll
    for (int i = 0; i < NS; i++)
        v[i] = samples[i * PIXELS + t];
    float y = target[t];
    float acc = crps_vals(v, y);

    // ---- batches 1..3 from smem, draining the pipeline in order ----
    asm volatile("cp.async.wait_group 2;" ::: "memory");
#pragma unroll
    for (int i = 0; i < NS; i++) v[i] = stage[0][i][tid];
    acc += crps_vals(v, stage[0][NS][tid]);

    asm volatile("cp.async.wait_group 1;" ::: "memory");
#pragma unroll
    for (int i = 0; i < NS; i++) v[i] = stage[1][i][tid];
    acc += crps_vals(v, stage[1][NS][tid]);

    asm volatile("cp.async.wait_group 0;" ::: "memory");
#pragma unroll
    for (int i = 0; i < NS; i++) v[i] = stage[2][i][tid];
    acc += crps_vals(v, stage[2][NS][tid]);

    // ---- block reduction ----
#pragma unroll
    for (int off = 16; off > 0; off >>= 1)
        acc += __shfl_down_sync(0xFFFFFFFFu, acc, off);

    __shared__ float warp_sums[TPB / 32];
    const int lane = tid & 31;
    const int wid  = tid >> 5;
    if (lane == 0) warp_sums[wid] = acc;
    __syncthreads();

    __shared__ bool is_last;
    if (tid == 0) {
        float bsum = 0.f;
#pragma unroll
        for (int w = 0; w < TPB / 32; w++)
            bsum += warp_sums[w];
        g_partials[blockIdx.x] = bsum;
        __threadfence();
        unsigned int done = atomicAdd(&g_count, 1u);
        is_last = (done == NBLOCKS - 1);
    }
    __syncthreads();

    // ---- last block folds all 256 partials in a fixed order ----
    if (is_last) {
        float s = g_partials[tid];
#pragma unroll
        for (int off = 16; off > 0; off >>= 1)
            s += __shfl_down_sync(0xFFFFFFFFu, s, off);
        if (lane == 0) warp_sums[wid] = s;
        __syncthreads();
        if (wid == 0) {
            float tot = (lane < TPB / 32) ? warp_sums[lane] : 0.f;
#pragma unroll
            for (int off = 4; off > 0; off >>= 1)
                tot += __shfl_down_sync(0xFFFFFFFFu, tot, off);
            if (lane == 0) {
                out[0] = tot * (1.f / PIXELS);
                g_count = 0;   // reset for next graph replay
            }
        }
    }
}

extern "C" void kernel_launch(void* const* d_in, const int* in_sizes, int n_in,
                              void* d_out, int out_size)
{
    const float* samples = (const float*)d_in[0];
    const float* target  = (const float*)d_in[1];
    float* out = (float*)d_out;

    crps_fused_kernel<<<NBLOCKS, TPB>>>(samples, target, out);
}